// round 15
// baseline (speedup 1.0000x reference)
#include <cuda_runtime.h>
#include <cuda_bf16.h>
#include <math.h>
#include <stdint.h>

#define CN 512
#define HW 1024
#define BTN 32
#define NSP 32768               // 32*1024 = 2048*16
#define GROUPS 32
#define ATT_SCALE 0.044194173824159216f   // 512^-0.5
#define GN_EPS 1e-6f

// ------------------------------ scratch (device globals, no allocs) ---------
__device__ float g_s [CN * NSP];                  // state after spatial residual
__device__ float g_attn[(size_t)BTN * HW * HW];   // fp32 logits
__device__ float g_ps [BTN * GROUPS * HW];
__device__ float g_ps2[BTN * GROUPS * HW];
__device__ float g_mean[2048 * GROUPS];
__device__ float g_rstd[2048 * GROUPS];
__device__ __nv_bfloat16 g_hsb[(size_t)CN * NSP];     // normed acts  [c][n]
__device__ __nv_bfloat16 g_qb [(size_t)CN * NSP];
__device__ __nv_bfloat16 g_kb [(size_t)CN * NSP];
__device__ __nv_bfloat16 g_vb [(size_t)CN * NSP];
__device__ __nv_bfloat16 g_ob [(size_t)CN * NSP];
__device__ __nv_bfloat16 g_attnb[(size_t)BTN * HW * HW];  // bf16 probs [qp][kp]
__device__ __nv_bfloat16 g_wb [8 * CN * CN];              // bf16 weights [m][k]

// ------------------------------ asm helpers ---------------------------------
__device__ __forceinline__ uint32_t smem_u32(const void* p) {
    uint32_t a;
    asm("{ .reg .u64 t; cvta.to.shared.u64 t, %1; cvt.u32.u64 %0, t; }"
        : "=r"(a) : "l"(p));
    return a;
}
#define CP16(dst, src) \
    asm volatile("cp.async.cg.shared.global [%0], [%1], 16;" :: "r"(dst), "l"(src))
#define CP_COMMIT() asm volatile("cp.async.commit_group;" ::: "memory")
#define CP_WAIT1()  asm volatile("cp.async.wait_group 1;"  ::: "memory")
#define CP_WAIT0()  asm volatile("cp.async.wait_group 0;"  ::: "memory")

__device__ __forceinline__ void ldsm4(uint32_t* r, uint32_t a) {
    asm volatile("ldmatrix.sync.aligned.m8n8.x4.shared.b16 {%0,%1,%2,%3}, [%4];"
                 : "=r"(r[0]), "=r"(r[1]), "=r"(r[2]), "=r"(r[3]) : "r"(a));
}
__device__ __forceinline__ void ldsm4t(uint32_t* r, uint32_t a) {
    asm volatile("ldmatrix.sync.aligned.m8n8.x4.trans.shared.b16 {%0,%1,%2,%3}, [%4];"
                 : "=r"(r[0]), "=r"(r[1]), "=r"(r[2]), "=r"(r[3]) : "r"(a));
}
__device__ __forceinline__ void mma_bf16(float* d, const uint32_t* a, uint32_t b0, uint32_t b1) {
    asm volatile(
        "mma.sync.aligned.m16n8k16.row.col.f32.bf16.bf16.f32 "
        "{%0,%1,%2,%3}, {%4,%5,%6,%7}, {%8,%9}, {%0,%1,%2,%3};"
        : "+f"(d[0]), "+f"(d[1]), "+f"(d[2]), "+f"(d[3])
        : "r"(a[0]), "r"(a[1]), "r"(a[2]), "r"(a[3]), "r"(b0), "r"(b1));
}
// swizzles: A-style tiles have 128B rows (64 bf16), B-style 256B rows (128 bf16)
__device__ __forceinline__ uint32_t swzA(int r, int c16) {
    return (uint32_t)(r * 128 + ((c16 ^ (r & 7)) << 4));
}
__device__ __forceinline__ uint32_t swzB(int r, int c16) {
    return (uint32_t)(r * 256 + ((c16 ^ (r & 7)) << 4));
}

#define STAGE_BYTES 32768   // 16KB A + 16KB B
#define SMEM_TOT (3 * STAGE_BYTES)

// ===================== fused QKV projection GEMM ============================
// blockIdx.z selects {Wq,Wk,Wv} (contiguous in WbBase) / bias / Out.
__global__ void __launch_bounds__(256, 2) gemm_qkv(
    const __nv_bfloat16* __restrict__ WbBase,
    const float* __restrict__ bq, const float* __restrict__ bk,
    const float* __restrict__ bv,
    const __nv_bfloat16* __restrict__ Xb,
    __nv_bfloat16* __restrict__ Oq, __nv_bfloat16* __restrict__ Ok,
    __nv_bfloat16* __restrict__ Ov)
{
    extern __shared__ __align__(16) char sm[];
    const uint32_t sb = smem_u32(sm);
    const int tid = threadIdx.x, lane = tid & 31, wid = tid >> 5;
    const int wm = wid & 1, wn = wid >> 1;
    const int n0 = blockIdx.x << 7, m0 = blockIdx.y << 7;
    const int z = blockIdx.z;
    const __nv_bfloat16* Wb = WbBase + (size_t)z * CN * CN;
    const float* bias = (z == 0) ? bq : (z == 1) ? bk : bv;
    __nv_bfloat16* OutB = (z == 0) ? Oq : (z == 1) ? Ok : Ov;

    auto issue = [&](int kc, int st) {
        uint32_t sA = sb + st * STAGE_BYTES;
        uint32_t sB = sA + 16384;
#pragma unroll
        for (int i = 0; i < 4; i++) {
            int ch = tid + (i << 8);
            int rA = ch >> 3, cA = ch & 7;
            CP16(sA + swzA(rA, cA),
                 Wb + (size_t)(m0 + rA) * 512 + (kc << 6) + (cA << 3));
            int rB = ch >> 4, cB = ch & 15;
            CP16(sB + swzB(rB, cB),
                 Xb + (size_t)((kc << 6) + rB) * NSP + n0 + (cB << 3));
        }
    };

    float acc[4][4][4] = {};
    issue(0, 0); CP_COMMIT();
    issue(1, 1); CP_COMMIT();
    const int NK = 8;
    for (int s = 0; s < NK; s++) {
        CP_WAIT1();
        __syncthreads();
        if (s + 2 < NK) issue(s + 2, (s + 2) % 3);
        CP_COMMIT();
        uint32_t sA = sb + (s % 3) * STAGE_BYTES, sB = sA + 16384;
#pragma unroll
        for (int kk = 0; kk < 4; kk++) {
            uint32_t af[4][4], bf[2][4];
#pragma unroll
            for (int mt = 0; mt < 4; mt++) {
                int r = (wm << 6) + (mt << 4) + (lane & 15);
                int c16 = (kk << 1) + ((lane >> 4) & 1);
                ldsm4(af[mt], sA + swzA(r, c16));
            }
#pragma unroll
            for (int nb = 0; nb < 2; nb++) {
                int r = (kk << 4) + (lane & 15);
                int c16 = (wn << 2) + (nb << 1) + ((lane >> 4) & 1);
                ldsm4t(bf[nb], sB + swzB(r, c16));
            }
#pragma unroll
            for (int mt = 0; mt < 4; mt++)
#pragma unroll
                for (int ng = 0; ng < 4; ng++)
                    mma_bf16(acc[mt][ng], af[mt],
                             bf[ng >> 1][(ng & 1) << 1], bf[ng >> 1][((ng & 1) << 1) + 1]);
        }
    }

    const int g = lane >> 2, tig = lane & 3;
#pragma unroll
    for (int mt = 0; mt < 4; mt++) {
        int mlo = m0 + (wm << 6) + (mt << 4) + g;
        float blo = __ldg(bias + mlo), bhi = __ldg(bias + mlo + 8);
#pragma unroll
        for (int ng = 0; ng < 4; ng++) {
            int n = n0 + (wn << 5) + (ng << 3) + (tig << 1);
            float* d = acc[mt][ng];
            __nv_bfloat162 plo = __floats2bfloat162_rn(d[0] + blo, d[1] + blo);
            __nv_bfloat162 phi = __floats2bfloat162_rn(d[2] + bhi, d[3] + bhi);
            *(__nv_bfloat162*)(OutB + (size_t)mlo * NSP + n) = plo;
            *(__nv_bfloat162*)(OutB + (size_t)(mlo + 8) * NSP + n) = phi;
        }
    }
}

// ===================== o-projection GEMM ====================================
// mode 1: fp32 out [c][nsp] + residual (x-layout) + FUSED tstats1 partial sums
// mode 3: write directly to x-layout output with residual from Res ([c][nsp])
__global__ void __launch_bounds__(256, 2) gemm_proj(
    const __nv_bfloat16* __restrict__ Wb, const float* __restrict__ bias,
    const __nv_bfloat16* __restrict__ Xb,
    float* __restrict__ OutF, const float* __restrict__ Res, int mode)
{
    extern __shared__ __align__(16) char sm[];
    const uint32_t sb = smem_u32(sm);
    const int tid = threadIdx.x, lane = tid & 31, wid = tid >> 5;
    const int wm = wid & 1, wn = wid >> 1;
    const int n0 = blockIdx.x << 7, m0 = blockIdx.y << 7;

    auto issue = [&](int kc, int st) {
        uint32_t sA = sb + st * STAGE_BYTES;
        uint32_t sB = sA + 16384;
#pragma unroll
        for (int i = 0; i < 4; i++) {
            int ch = tid + (i << 8);
            int rA = ch >> 3, cA = ch & 7;
            CP16(sA + swzA(rA, cA),
                 Wb + (size_t)(m0 + rA) * 512 + (kc << 6) + (cA << 3));
            int rB = ch >> 4, cB = ch & 15;
            CP16(sB + swzB(rB, cB),
                 Xb + (size_t)((kc << 6) + rB) * NSP + n0 + (cB << 3));
        }
    };

    float acc[4][4][4] = {};
    issue(0, 0); CP_COMMIT();
    issue(1, 1); CP_COMMIT();
    const int NK = 8;
    for (int s = 0; s < NK; s++) {
        CP_WAIT1();
        __syncthreads();
        if (s + 2 < NK) issue(s + 2, (s + 2) % 3);
        CP_COMMIT();
        uint32_t sA = sb + (s % 3) * STAGE_BYTES, sB = sA + 16384;
#pragma unroll
        for (int kk = 0; kk < 4; kk++) {
            uint32_t af[4][4], bf[2][4];
#pragma unroll
            for (int mt = 0; mt < 4; mt++) {
                int r = (wm << 6) + (mt << 4) + (lane & 15);
                int c16 = (kk << 1) + ((lane >> 4) & 1);
                ldsm4(af[mt], sA + swzA(r, c16));
            }
#pragma unroll
            for (int nb = 0; nb < 2; nb++) {
                int r = (kk << 4) + (lane & 15);
                int c16 = (wn << 2) + (nb << 1) + ((lane >> 4) & 1);
                ldsm4t(bf[nb], sB + swzB(r, c16));
            }
#pragma unroll
            for (int mt = 0; mt < 4; mt++)
#pragma unroll
                for (int ng = 0; ng < 4; ng++)
                    mma_bf16(acc[mt][ng], af[mt],
                             bf[ng >> 1][(ng & 1) << 1], bf[ng >> 1][((ng & 1) << 1) + 1]);
        }
    }

    const int g = lane >> 2, tig = lane & 3;
    if (mode == 1) {
        const int bt = n0 >> 10, bb = bt >> 4, tt = bt & 15;
#pragma unroll
        for (int mt = 0; mt < 4; mt++) {
            int mlo = m0 + (wm << 6) + (mt << 4) + g;
            float blo = __ldg(bias + mlo), bhi = __ldg(bias + mlo + 8);
#pragma unroll
            for (int ng = 0; ng < 4; ng++) {
                int n = n0 + (wn << 5) + (ng << 3) + (tig << 1);
                float* d = acc[mt][ng];
                float2 olo = make_float2(d[0] + blo, d[1] + blo);
                float2 ohi = make_float2(d[2] + bhi, d[3] + bhi);
                int hw = n & 1023;
                float2 rlo = *(const float2*)(Res +
                    (((size_t)((bb * CN + mlo) * 16 + tt)) << 10) + hw);
                float2 rhi = *(const float2*)(Res +
                    (((size_t)((bb * CN + mlo + 8) * 16 + tt)) << 10) + hw);
                olo.x += rlo.x; olo.y += rlo.y;
                ohi.x += rhi.x; ohi.y += rhi.y;
                *(float2*)(OutF + (size_t)mlo * NSP + n) = olo;
                *(float2*)(OutF + (size_t)(mlo + 8) * NSP + n) = ohi;
                float s0 = olo.x + ohi.x, s1 = olo.y + ohi.y;
                float q0 = olo.x * olo.x + ohi.x * ohi.x;
                float q1 = olo.y * olo.y + ohi.y * ohi.y;
#pragma unroll
                for (int off = 4; off <= 16; off <<= 1) {
                    s0 += __shfl_xor_sync(0xffffffffu, s0, off);
                    s1 += __shfl_xor_sync(0xffffffffu, s1, off);
                    q0 += __shfl_xor_sync(0xffffffffu, q0, off);
                    q1 += __shfl_xor_sync(0xffffffffu, q1, off);
                }
                if (g == 0) {
                    int grp = mlo >> 4;
                    size_t pbase = (((size_t)(bt * 32 + grp)) << 10) + hw;
                    g_ps [pbase]     = s0;
                    g_ps [pbase + 1] = s1;
                    g_ps2[pbase]     = q0;
                    g_ps2[pbase + 1] = q1;
                }
            }
        }
    } else {
        CP_WAIT0();
        __syncthreads();
        float* tile = (float*)sm;  // [128][129]
#pragma unroll
        for (int mt = 0; mt < 4; mt++) {
            int mrow = (wm << 6) + (mt << 4) + g;
            int mlo = m0 + mrow;
            float blo = __ldg(bias + mlo), bhi = __ldg(bias + mlo + 8);
#pragma unroll
            for (int ng = 0; ng < 4; ng++) {
                int nl = (wn << 5) + (ng << 3) + (tig << 1);
                float* d = acc[mt][ng];
                tile[mrow * 129 + nl]           = d[0] + blo;
                tile[mrow * 129 + nl + 1]       = d[1] + blo;
                tile[(mrow + 8) * 129 + nl]     = d[2] + bhi;
                tile[(mrow + 8) * 129 + nl + 1] = d[3] + bhi;
            }
        }
        __syncthreads();
        const int b = n0 >> 14;
        const int hw0 = (n0 >> 4) & 1023;
        for (int idx = tid; idx < 16384; idx += 256) {
            int hwl = idx & 7, t = (idx >> 3) & 15, m = idx >> 7;
            int c = m0 + m;
            float v = tile[m * 129 + hwl * 16 + t];
            float sres = Res[(size_t)c * NSP + ((size_t)((b << 4) + t) << 10) + hw0 + hwl];
            OutF[((size_t)((b * CN + c) * 16 + t) << 10) + hw0 + hwl] = v + sres;
        }
    }
}

// ===================== spatial logits GEMM ==================================
__global__ void __launch_bounds__(256, 2) gemm_logits(
    const __nv_bfloat16* __restrict__ Qb, const __nv_bfloat16* __restrict__ Kb,
    float* __restrict__ P)
{
    extern __shared__ __align__(16) char sm[];
    const uint32_t sb = smem_u32(sm);
    const int tid = threadIdx.x, lane = tid & 31, wid = tid >> 5;
    const int wm = wid & 1, wn = wid >> 1;
    const int n0 = blockIdx.x << 7, m0 = blockIdx.y << 7;
    const int base = blockIdx.z << 10;

    auto issue = [&](int kc, int st) {
        uint32_t sA = sb + st * STAGE_BYTES;
        uint32_t sB = sA + 16384;
#pragma unroll
        for (int i = 0; i < 4; i++) {
            int ch = tid + (i << 8);
            int r = ch >> 4, c = ch & 15;
            CP16(sA + swzB(r, c),
                 Qb + (size_t)((kc << 6) + r) * NSP + base + m0 + (c << 3));
            CP16(sB + swzB(r, c),
                 Kb + (size_t)((kc << 6) + r) * NSP + base + n0 + (c << 3));
        }
    };

    float acc[4][4][4] = {};
    issue(0, 0); CP_COMMIT();
    issue(1, 1); CP_COMMIT();
    const int NK = 8;
    for (int s = 0; s < NK; s++) {
        CP_WAIT1();
        __syncthreads();
        if (s + 2 < NK) issue(s + 2, (s + 2) % 3);
        CP_COMMIT();
        uint32_t sA = sb + (s % 3) * STAGE_BYTES, sB = sA + 16384;
#pragma unroll
        for (int kk = 0; kk < 4; kk++) {
            uint32_t af[4][4], bf[2][4];
#pragma unroll
            for (int mt = 0; mt < 4; mt++) {
                int r = (kk << 4) + (lane & 7) + (((lane >> 4) & 1) << 3);
                int c16 = (wm << 3) + (mt << 1) + ((lane >> 3) & 1);
                ldsm4t(af[mt], sA + swzB(r, c16));
            }
#pragma unroll
            for (int nb = 0; nb < 2; nb++) {
                int r = (kk << 4) + (lane & 15);
                int c16 = (wn << 2) + (nb << 1) + ((lane >> 4) & 1);
                ldsm4t(bf[nb], sB + swzB(r, c16));
            }
#pragma unroll
            for (int mt = 0; mt < 4; mt++)
#pragma unroll
                for (int ng = 0; ng < 4; ng++)
                    mma_bf16(acc[mt][ng], af[mt],
                             bf[ng >> 1][(ng & 1) << 1], bf[ng >> 1][((ng & 1) << 1) + 1]);
        }
    }

    float* Pb = P + ((size_t)blockIdx.z << 20);
    const int g = lane >> 2, tig = lane & 3;
#pragma unroll
    for (int mt = 0; mt < 4; mt++) {
        int mlo = m0 + (wm << 6) + (mt << 4) + g;
#pragma unroll
        for (int ng = 0; ng < 4; ng++) {
            int n = n0 + (wn << 5) + (ng << 3) + (tig << 1);
            float* d = acc[mt][ng];
            *(float2*)(Pb + (size_t)mlo * 1024 + n) =
                make_float2(d[0] * ATT_SCALE, d[1] * ATT_SCALE);
            *(float2*)(Pb + (size_t)(mlo + 8) * 1024 + n) =
                make_float2(d[2] * ATT_SCALE, d[3] * ATT_SCALE);
        }
    }
}

// ===================== attn @ V GEMM ========================================
__global__ void __launch_bounds__(256, 2) gemm_av(
    const __nv_bfloat16* __restrict__ Vb, const __nv_bfloat16* __restrict__ Pb,
    __nv_bfloat16* __restrict__ OutB)
{
    extern __shared__ __align__(16) char sm[];
    const uint32_t sb = smem_u32(sm);
    const int tid = threadIdx.x, lane = tid & 31, wid = tid >> 5;
    const int wm = wid & 1, wn = wid >> 1;
    const int n0 = blockIdx.x << 7, m0 = blockIdx.y << 7;
    const int base = blockIdx.z << 10;
    const __nv_bfloat16* Pt = Pb + ((size_t)blockIdx.z << 20);

    auto issue = [&](int kc, int st) {
        uint32_t sA = sb + st * STAGE_BYTES;
        uint32_t sB = sA + 16384;
#pragma unroll
        for (int i = 0; i < 4; i++) {
            int ch = tid + (i << 8);
            int r = ch >> 3, c = ch & 7;
            CP16(sA + swzA(r, c),
                 Vb + (size_t)(m0 + r) * NSP + base + (kc << 6) + (c << 3));
            CP16(sB + swzA(r, c),
                 Pt + (size_t)(n0 + r) * 1024 + (kc << 6) + (c << 3));
        }
    };

    float acc[4][4][4] = {};
    issue(0, 0); CP_COMMIT();
    issue(1, 1); CP_COMMIT();
    const int NK = 16;
    for (int s = 0; s < NK; s++) {
        CP_WAIT1();
        __syncthreads();
        if (s + 2 < NK) issue(s + 2, (s + 2) % 3);
        CP_COMMIT();
        uint32_t sA = sb + (s % 3) * STAGE_BYTES, sB = sA + 16384;
#pragma unroll
        for (int kk = 0; kk < 4; kk++) {
            uint32_t af[4][4], bf[2][4];
#pragma unroll
            for (int mt = 0; mt < 4; mt++) {
                int r = (wm << 6) + (mt << 4) + (lane & 15);
                int c16 = (kk << 1) + ((lane >> 4) & 1);
                ldsm4(af[mt], sA + swzA(r, c16));
            }
#pragma unroll
            for (int nb = 0; nb < 2; nb++) {
                int r = (wn << 5) + (nb << 4) + (lane & 7) + (((lane >> 4) & 1) << 3);
                int c16 = (kk << 1) + ((lane >> 3) & 1);
                ldsm4(bf[nb], sB + swzA(r, c16));
            }
#pragma unroll
            for (int mt = 0; mt < 4; mt++)
#pragma unroll
                for (int ng = 0; ng < 4; ng++)
                    mma_bf16(acc[mt][ng], af[mt],
                             bf[ng >> 1][(ng & 1) << 1], bf[ng >> 1][((ng & 1) << 1) + 1]);
        }
    }

    const int g = lane >> 2, tig = lane & 3;
#pragma unroll
    for (int mt = 0; mt < 4; mt++) {
        int mlo = m0 + (wm << 6) + (mt << 4) + g;
#pragma unroll
        for (int ng = 0; ng < 4; ng++) {
            int n = n0 + (wn << 5) + (ng << 3) + (tig << 1);
            float* d = acc[mt][ng];
            *(__nv_bfloat162*)(OutB + (size_t)mlo * NSP + base + n) =
                __floats2bfloat162_rn(d[0], d[1]);
            *(__nv_bfloat162*)(OutB + (size_t)(mlo + 8) * NSP + base + n) =
                __floats2bfloat162_rn(d[2], d[3]);
        }
    }
}

// ===================== weight fp32 -> bf16 (all 8 in one launch) ============
__global__ __launch_bounds__(256) void wcvt8(
    const float* w0, const float* w1, const float* w2, const float* w3,
    const float* w4, const float* w5, const float* w6, const float* w7,
    __nv_bfloat16* __restrict__ Wb)
{
    const float* ws[8] = {w0, w1, w2, w3, w4, w5, w6, w7};
    int wsel = blockIdx.y;
    int idx = (blockIdx.x * 256 + threadIdx.x) * 4;
    float4 v = *(const float4*)(ws[wsel] + idx);
    __nv_bfloat162 p0 = __floats2bfloat162_rn(v.x, v.y);
    __nv_bfloat162 p1 = __floats2bfloat162_rn(v.z, v.w);
    uint2 o;
    o.x = *(uint32_t*)&p0; o.y = *(uint32_t*)&p1;
    *(uint2*)(Wb + (size_t)wsel * CN * CN + idx) = o;
}

// ===================== spatial GroupNorm -> bf16 [c][n] (single pass) =======
__global__ __launch_bounds__(256) void gn_spatial(
    const float* __restrict__ x, const float* __restrict__ gamma,
    const float* __restrict__ beta, __nv_bfloat16* __restrict__ hsb)
{
    int bt = blockIdx.x >> 5, g = blockIdx.x & 31;
    int b = bt >> 4, t = bt & 15;
    int tid = threadIdx.x;
    float2 v[16][2];
    float s = 0.f, s2 = 0.f;
#pragma unroll
    for (int ci = 0; ci < 16; ci++) {
        const float* p = x + ((size_t)((b * CN + g * 16 + ci) * 16 + t) << 10);
#pragma unroll
        for (int j = 0; j < 2; j++) {
            float2 vv = *(const float2*)(p + 2 * tid + 512 * j);
            v[ci][j] = vv;
            s += vv.x + vv.y; s2 += vv.x * vv.x + vv.y * vv.y;
        }
    }
    __shared__ float red0[8], red1[8];
#pragma unroll
    for (int off = 16; off; off >>= 1) {
        s  += __shfl_xor_sync(0xffffffffu, s,  off);
        s2 += __shfl_xor_sync(0xffffffffu, s2, off);
    }
    if ((tid & 31) == 0) { red0[tid >> 5] = s; red1[tid >> 5] = s2; }
    __syncthreads();
    float S = 0.f, S2 = 0.f;
#pragma unroll
    for (int i = 0; i < 8; i++) { S += red0[i]; S2 += red1[i]; }
    float mean = S * (1.f / 16384.f);
    float var  = S2 * (1.f / 16384.f) - mean * mean;
    float rstd = rsqrtf(var + GN_EPS);
#pragma unroll
    for (int ci = 0; ci < 16; ci++) {
        int c = g * 16 + ci;
        __nv_bfloat16* q = hsb + (size_t)c * NSP + (bt << 10);
        float gm = gamma[c] * rstd, be = beta[c] - mean * gamma[c] * rstd;
#pragma unroll
        for (int j = 0; j < 2; j++) {
            *(__nv_bfloat162*)(q + 2 * tid + 512 * j) =
                __floats2bfloat162_rn(v[ci][j].x * gm + be, v[ci][j].y * gm + be);
        }
    }
}

// ===================== spatial softmax (fp32 -> bf16) =======================
__global__ __launch_bounds__(256) void softmax_k(const float* __restrict__ P,
                                                 __nv_bfloat16* __restrict__ Pb)
{
    int tid = threadIdx.x;
    const float4* r = (const float4*)(P + ((size_t)blockIdx.x << 10));
    float4 a = r[tid];
    float m = fmaxf(fmaxf(a.x, a.y), fmaxf(a.z, a.w));
    __shared__ float red[8];
#pragma unroll
    for (int off = 16; off; off >>= 1) m = fmaxf(m, __shfl_xor_sync(0xffffffffu, m, off));
    if ((tid & 31) == 0) red[tid >> 5] = m;
    __syncthreads();
    float M = red[0];
#pragma unroll
    for (int i = 1; i < 8; i++) M = fmaxf(M, red[i]);
    a.x = __expf(a.x - M); a.y = __expf(a.y - M);
    a.z = __expf(a.z - M); a.w = __expf(a.w - M);
    float s = a.x + a.y + a.z + a.w;
    __syncthreads();
#pragma unroll
    for (int off = 16; off; off >>= 1) s += __shfl_xor_sync(0xffffffffu, s, off);
    if ((tid & 31) == 0) red[tid >> 5] = s;
    __syncthreads();
    float S = red[0];
#pragma unroll
    for (int i = 1; i < 8; i++) S += red[i];
    float inv = 1.f / S;
    __nv_bfloat162 p0 = __floats2bfloat162_rn(a.x * inv, a.y * inv);
    __nv_bfloat162 p1 = __floats2bfloat162_rn(a.z * inv, a.w * inv);
    uint2 o; o.x = *(uint32_t*)&p0; o.y = *(uint32_t*)&p1;
    *(uint2*)(Pb + ((size_t)blockIdx.x << 10) + 4 * tid) = o;
}

// ===================== temporal stats (pass 2 only; pass 1 fused) ===========
__global__ __launch_bounds__(256) void tstats2()
{
    int hwc = blockIdx.x & 3, g = (blockIdx.x >> 2) & 31, b = blockIdx.x >> 7;
    int hw = (hwc << 8) + threadIdx.x;
    float s = 0.f, s2 = 0.f;
#pragma unroll
    for (int t = 0; t < 16; t++) {
        int idx = (((b * 16 + t) * 32 + g) << 10) + hw;
        s += g_ps[idx]; s2 += g_ps2[idx];
    }
    float mean = s * (1.f / 256.f);
    float var  = s2 * (1.f / 256.f) - mean * mean;
    int n = (b << 10) + hw;
    g_mean[n * 32 + g] = mean;
    g_rstd[n * 32 + g] = rsqrtf(var + GN_EPS);
}

// normalize + transpose into bf16 ht[c][(b,hw)*16+t]
__global__ __launch_bounds__(256) void tnorm(
    const float* __restrict__ S, const float* __restrict__ gamma,
    const float* __restrict__ beta, __nv_bfloat16* __restrict__ ht)
{
    __shared__ float sm[4 * 2176];
    __shared__ float smean[128], srstd[128];
    int hw0 = blockIdx.x << 7, c0 = blockIdx.y << 2, b = blockIdx.z;
    int g = c0 >> 4;
    int tid = threadIdx.x;
    if (tid < 128) {
        int n = (b << 10) + hw0 + tid;
        smean[tid] = g_mean[n * 32 + g];
        srstd[tid] = g_rstd[n * 32 + g];
    }
    __syncthreads();
    for (int idx = tid; idx < 8192; idx += 256) {
        int c = idx >> 11, rem = idx & 2047, t = rem >> 7, col = rem & 127;
        float v = S[(size_t)(c0 + c) * NSP + ((size_t)((b << 4) + t) << 10) + hw0 + col];
        float h = (v - smean[col]) * srstd[col] * gamma[c0 + c] + beta[c0 + c];
        sm[c * 2176 + col * 17 + t] = h;
    }
    __syncthreads();
    size_t base = (size_t)((b << 10) + hw0) << 4;
    for (int idx = tid; idx < 4096; idx += 256) {
        int c = idx >> 10, j2 = (idx & 1023) << 1;
        float v0 = sm[c * 2176 + ((j2 >> 4) * 17) + (j2 & 15)];
        float v1 = sm[c * 2176 + ((j2 >> 4) * 17) + (j2 & 15) + 1];
        *(__nv_bfloat162*)(ht + (size_t)(c0 + c) * NSP + base + j2) =
            __floats2bfloat162_rn(v0, v1);
    }
}

// ===================== temporal attention (fused, bf16 io) ==================
__global__ __launch_bounds__(256) void temporal_attn(
    const __nv_bfloat16* __restrict__ Q, const __nv_bfloat16* __restrict__ K,
    const __nv_bfloat16* __restrict__ V, __nv_bfloat16* __restrict__ O)
{
    __shared__ float sq[16][16], sk[16][16], sv[16][16], sp[16][17];
    int col0 = blockIdx.x << 4;
    int tid = threadIdx.x, hi = tid >> 4, lo = tid & 15;
    float acc = 0.f;
    for (int c0 = 0; c0 < 512; c0 += 16) {
        sq[hi][lo] = __bfloat162float(Q[(size_t)(c0 + hi) * NSP + col0 + lo]);
        sk[hi][lo] = __bfloat162float(K[(size_t)(c0 + hi) * NSP + col0 + lo]);
        __syncthreads();
#pragma unroll
        for (int cc = 0; cc < 16; cc++)
            acc = fmaf(sq[cc][hi], sk[cc][lo], acc);
        __syncthreads();
    }
    sp[hi][lo] = acc * ATT_SCALE;
    __syncthreads();
    if (tid < 16) {
        float m = -1e30f;
#pragma unroll
        for (int j = 0; j < 16; j++) m = fmaxf(m, sp[tid][j]);
        float s = 0.f;
#pragma unroll
        for (int j = 0; j < 16; j++) {
            float e = __expf(sp[tid][j] - m);
            sp[tid][j] = e; s += e;
        }
        float inv = 1.f / s;
#pragma unroll
        for (int j = 0; j < 16; j++) sp[tid][j] *= inv;
    }
    __syncthreads();
    for (int c0 = 0; c0 < 512; c0 += 16) {
        sv[hi][lo] = __bfloat162float(V[(size_t)(c0 + hi) * NSP + col0 + lo]);
        __syncthreads();
        float o = 0.f;
#pragma unroll
        for (int t2 = 0; t2 < 16; t2++)
            o = fmaf(sv[hi][t2], sp[lo][t2], o);
        O[(size_t)(c0 + hi) * NSP + col0 + lo] = __float2bfloat16(o);
        __syncthreads();
    }
}

// ===================== launch ===============================================
extern "C" void kernel_launch(void* const* d_in, const int* in_sizes, int n_in,
                              void* d_out, int out_size)
{
    const float* x       = (const float*)d_in[0];
    const float* gamma_s = (const float*)d_in[1];
    const float* beta_s  = (const float*)d_in[2];
    const float* wq_s    = (const float*)d_in[3];
    const float* bq_s    = (const float*)d_in[4];
    const float* wk_s    = (const float*)d_in[5];
    const float* bk_s    = (const float*)d_in[6];
    const float* wv_s    = (const float*)d_in[7];
    const float* bv_s    = (const float*)d_in[8];
    const float* wo_s    = (const float*)d_in[9];
    const float* bo_s    = (const float*)d_in[10];
    const float* gamma_t = (const float*)d_in[11];
    const float* beta_t  = (const float*)d_in[12];
    const float* wq_t    = (const float*)d_in[13];
    const float* bq_t    = (const float*)d_in[14];
    const float* wk_t    = (const float*)d_in[15];
    const float* bk_t    = (const float*)d_in[16];
    const float* wv_t    = (const float*)d_in[17];
    const float* bv_t    = (const float*)d_in[18];
    const float* wo_t    = (const float*)d_in[19];
    const float* bo_t    = (const float*)d_in[20];

    float *s, *attn;
    __nv_bfloat16 *hsb, *qb, *kb, *vb, *ob, *attnb, *wb;
    cudaGetSymbolAddress((void**)&s,     g_s);
    cudaGetSymbolAddress((void**)&attn,  g_attn);
    cudaGetSymbolAddress((void**)&hsb,   g_hsb);
    cudaGetSymbolAddress((void**)&qb,    g_qb);
    cudaGetSymbolAddress((void**)&kb,    g_kb);
    cudaGetSymbolAddress((void**)&vb,    g_vb);
    cudaGetSymbolAddress((void**)&ob,    g_ob);
    cudaGetSymbolAddress((void**)&attnb, g_attnb);
    cudaGetSymbolAddress((void**)&wb,    g_wb);

    cudaFuncSetAttribute(gemm_qkv,    cudaFuncAttributeMaxDynamicSharedMemorySize, SMEM_TOT);
    cudaFuncSetAttribute(gemm_proj,   cudaFuncAttributeMaxDynamicSharedMemorySize, SMEM_TOT);
    cudaFuncSetAttribute(gemm_logits, cudaFuncAttributeMaxDynamicSharedMemorySize, SMEM_TOT);
    cudaFuncSetAttribute(gemm_av,     cudaFuncAttributeMaxDynamicSharedMemorySize, SMEM_TOT);

    // side stream + events: created once on the first (non-captured) call.
    static cudaStream_t s2 = nullptr;
    static cudaEvent_t eRoot = nullptr, eW = nullptr, eGN = nullptr, eV = nullptr;
    if (!s2) {
        cudaStreamCreateWithFlags(&s2, cudaStreamNonBlocking);
        cudaEventCreateWithFlags(&eRoot, cudaEventDisableTiming);
        cudaEventCreateWithFlags(&eW,    cudaEventDisableTiming);
        cudaEventCreateWithFlags(&eGN,   cudaEventDisableTiming);
        cudaEventCreateWithFlags(&eV,    cudaEventDisableTiming);
    }

    dim3 gqk(256, 4, 2);    // q,k only
    dim3 gv(256, 4, 1);     // v only (side stream)
    dim3 gqkv(256, 4, 3);
    dim3 gp(256, 4);

    // ---- spatial: capture-legal fork (side branch ROOTED in origin stream) --
    cudaEventRecord(eRoot, (cudaStream_t)0);           // root the fork
    cudaStreamWaitEvent(s2, eRoot, 0);
    wcvt8<<<dim3(256, 8), 256, 0, s2>>>(wq_s, wk_s, wv_s, wo_s, wq_t, wk_t, wv_t, wo_t, wb);
    cudaEventRecord(eW, s2);
    gn_spatial<<<1024, 256>>>(x, gamma_s, beta_s, hsb);
    cudaEventRecord(eGN, (cudaStream_t)0);
    cudaStreamWaitEvent((cudaStream_t)0, eW, 0);       // weights ready for qk
    gemm_qkv<<<gqk, 256, SMEM_TOT>>>(wb, bq_s, bk_s, bv_s, hsb, qb, kb, vb);
    cudaStreamWaitEvent(s2, eGN, 0);                   // hsb ready for v (eW already in s2 order)
    gemm_qkv<<<gv, 256, SMEM_TOT, s2>>>(wb + 2 * CN * CN, bv_s, bv_s, bv_s,
                                        hsb, vb, vb, vb);
    cudaEventRecord(eV, s2);
    gemm_logits<<<dim3(8, 8, 32), 256, SMEM_TOT>>>(qb, kb, attn);
    softmax_k<<<32768, 256>>>(attn, attnb);
    cudaStreamWaitEvent((cudaStream_t)0, eV, 0);       // join: v ready
    gemm_av<<<dim3(8, 4, 32), 256, SMEM_TOT>>>(vb, attnb, ob);
    gemm_proj<<<gp, 256, SMEM_TOT>>>(wb + 3 * CN * CN, bo_s, ob, s, x, 1);  // +tstats1

    // ---- temporal ----
    tstats2<<<256, 256>>>();
    tnorm<<<dim3(8, 128, 2), 256>>>(s, gamma_t, beta_t, hsb);
    gemm_qkv<<<gqkv, 256, SMEM_TOT>>>(wb + 4 * CN * CN, bq_t, bk_t, bv_t, hsb, qb, kb, vb);
    temporal_attn<<<2048, 256>>>(qb, kb, vb, ob);
    gemm_proj<<<gp, 256, SMEM_TOT>>>(wb + 7 * CN * CN, bo_t, ob, (float*)d_out, s, 3);
}

// round 16
// speedup vs baseline: 1.0583x; 1.0583x over previous
#include <cuda_runtime.h>
#include <cuda_bf16.h>
#include <math.h>
#include <stdint.h>

#define CN 512
#define HW 1024
#define BTN 32
#define NSP 32768               // 32*1024 = 2048*16
#define GROUPS 32
#define ATT_SCALE 0.044194173824159216f   // 512^-0.5
#define GN_EPS 1e-6f

// ------------------------------ scratch (device globals, no allocs) ---------
__device__ float g_s [CN * NSP];                  // state after spatial residual
__device__ float g_attn[(size_t)BTN * HW * HW];   // fp32 logits
__device__ float g_ps [BTN * GROUPS * HW];
__device__ float g_ps2[BTN * GROUPS * HW];
__device__ float g_mean[2048 * GROUPS];
__device__ float g_rstd[2048 * GROUPS];
__device__ __nv_bfloat16 g_hsb[(size_t)CN * NSP];     // normed acts  [c][n]
__device__ __nv_bfloat16 g_qb [(size_t)CN * NSP];
__device__ __nv_bfloat16 g_kb [(size_t)CN * NSP];
__device__ __nv_bfloat16 g_vb [(size_t)CN * NSP];
__device__ __nv_bfloat16 g_ob [(size_t)CN * NSP];
__device__ __nv_bfloat16 g_attnb[(size_t)BTN * HW * HW];  // bf16 probs [qp][kp]
__device__ __nv_bfloat16 g_wb [8 * CN * CN];              // bf16 weights [m][k]

// ------------------------------ asm helpers ---------------------------------
__device__ __forceinline__ uint32_t smem_u32(const void* p) {
    uint32_t a;
    asm("{ .reg .u64 t; cvta.to.shared.u64 t, %1; cvt.u32.u64 %0, t; }"
        : "=r"(a) : "l"(p));
    return a;
}
#define CP16(dst, src) \
    asm volatile("cp.async.cg.shared.global [%0], [%1], 16;" :: "r"(dst), "l"(src))
#define CP_COMMIT() asm volatile("cp.async.commit_group;" ::: "memory")
#define CP_WAIT1()  asm volatile("cp.async.wait_group 1;"  ::: "memory")
#define CP_WAIT0()  asm volatile("cp.async.wait_group 0;"  ::: "memory")

__device__ __forceinline__ void ldsm4(uint32_t* r, uint32_t a) {
    asm volatile("ldmatrix.sync.aligned.m8n8.x4.shared.b16 {%0,%1,%2,%3}, [%4];"
                 : "=r"(r[0]), "=r"(r[1]), "=r"(r[2]), "=r"(r[3]) : "r"(a));
}
__device__ __forceinline__ void ldsm4t(uint32_t* r, uint32_t a) {
    asm volatile("ldmatrix.sync.aligned.m8n8.x4.trans.shared.b16 {%0,%1,%2,%3}, [%4];"
                 : "=r"(r[0]), "=r"(r[1]), "=r"(r[2]), "=r"(r[3]) : "r"(a));
}
__device__ __forceinline__ void mma_bf16(float* d, const uint32_t* a, uint32_t b0, uint32_t b1) {
    asm volatile(
        "mma.sync.aligned.m16n8k16.row.col.f32.bf16.bf16.f32 "
        "{%0,%1,%2,%3}, {%4,%5,%6,%7}, {%8,%9}, {%0,%1,%2,%3};"
        : "+f"(d[0]), "+f"(d[1]), "+f"(d[2]), "+f"(d[3])
        : "r"(a[0]), "r"(a[1]), "r"(a[2]), "r"(a[3]), "r"(b0), "r"(b1));
}
// swizzles: A-style tiles have 128B rows (64 bf16), B-style 256B rows (128 bf16)
__device__ __forceinline__ uint32_t swzA(int r, int c16) {
    return (uint32_t)(r * 128 + ((c16 ^ (r & 7)) << 4));
}
__device__ __forceinline__ uint32_t swzB(int r, int c16) {
    return (uint32_t)(r * 256 + ((c16 ^ (r & 7)) << 4));
}

#define STAGE_BYTES 32768   // 16KB A + 16KB B
#define SMEM_TOT (3 * STAGE_BYTES)
#define TA_SMEM 50752       // qT 16x520 bf16 + kT 16x520 bf16 + v 512x16 bf16 + p 16x17 f32

// ===================== fused QKV projection GEMM ============================
// blockIdx.z selects {Wq,Wk,Wv} (contiguous in WbBase) / bias / Out.
__global__ void __launch_bounds__(256, 2) gemm_qkv(
    const __nv_bfloat16* __restrict__ WbBase,
    const float* __restrict__ bq, const float* __restrict__ bk,
    const float* __restrict__ bv,
    const __nv_bfloat16* __restrict__ Xb,
    __nv_bfloat16* __restrict__ Oq, __nv_bfloat16* __restrict__ Ok,
    __nv_bfloat16* __restrict__ Ov)
{
    extern __shared__ __align__(16) char sm[];
    const uint32_t sb = smem_u32(sm);
    const int tid = threadIdx.x, lane = tid & 31, wid = tid >> 5;
    const int wm = wid & 1, wn = wid >> 1;
    const int n0 = blockIdx.x << 7, m0 = blockIdx.y << 7;
    const int z = blockIdx.z;
    const __nv_bfloat16* Wb = WbBase + (size_t)z * CN * CN;
    const float* bias = (z == 0) ? bq : (z == 1) ? bk : bv;
    __nv_bfloat16* OutB = (z == 0) ? Oq : (z == 1) ? Ok : Ov;

    auto issue = [&](int kc, int st) {
        uint32_t sA = sb + st * STAGE_BYTES;
        uint32_t sB = sA + 16384;
#pragma unroll
        for (int i = 0; i < 4; i++) {
            int ch = tid + (i << 8);
            int rA = ch >> 3, cA = ch & 7;
            CP16(sA + swzA(rA, cA),
                 Wb + (size_t)(m0 + rA) * 512 + (kc << 6) + (cA << 3));
            int rB = ch >> 4, cB = ch & 15;
            CP16(sB + swzB(rB, cB),
                 Xb + (size_t)((kc << 6) + rB) * NSP + n0 + (cB << 3));
        }
    };

    float acc[4][4][4] = {};
    issue(0, 0); CP_COMMIT();
    issue(1, 1); CP_COMMIT();
    const int NK = 8;
    for (int s = 0; s < NK; s++) {
        CP_WAIT1();
        __syncthreads();
        if (s + 2 < NK) issue(s + 2, (s + 2) % 3);
        CP_COMMIT();
        uint32_t sA = sb + (s % 3) * STAGE_BYTES, sB = sA + 16384;
#pragma unroll
        for (int kk = 0; kk < 4; kk++) {
            uint32_t af[4][4], bf[2][4];
#pragma unroll
            for (int mt = 0; mt < 4; mt++) {
                int r = (wm << 6) + (mt << 4) + (lane & 15);
                int c16 = (kk << 1) + ((lane >> 4) & 1);
                ldsm4(af[mt], sA + swzA(r, c16));
            }
#pragma unroll
            for (int nb = 0; nb < 2; nb++) {
                int r = (kk << 4) + (lane & 15);
                int c16 = (wn << 2) + (nb << 1) + ((lane >> 4) & 1);
                ldsm4t(bf[nb], sB + swzB(r, c16));
            }
#pragma unroll
            for (int mt = 0; mt < 4; mt++)
#pragma unroll
                for (int ng = 0; ng < 4; ng++)
                    mma_bf16(acc[mt][ng], af[mt],
                             bf[ng >> 1][(ng & 1) << 1], bf[ng >> 1][((ng & 1) << 1) + 1]);
        }
    }

    const int g = lane >> 2, tig = lane & 3;
#pragma unroll
    for (int mt = 0; mt < 4; mt++) {
        int mlo = m0 + (wm << 6) + (mt << 4) + g;
        float blo = __ldg(bias + mlo), bhi = __ldg(bias + mlo + 8);
#pragma unroll
        for (int ng = 0; ng < 4; ng++) {
            int n = n0 + (wn << 5) + (ng << 3) + (tig << 1);
            float* d = acc[mt][ng];
            __nv_bfloat162 plo = __floats2bfloat162_rn(d[0] + blo, d[1] + blo);
            __nv_bfloat162 phi = __floats2bfloat162_rn(d[2] + bhi, d[3] + bhi);
            *(__nv_bfloat162*)(OutB + (size_t)mlo * NSP + n) = plo;
            *(__nv_bfloat162*)(OutB + (size_t)(mlo + 8) * NSP + n) = phi;
        }
    }
}

// ===================== o-projection GEMM ====================================
// mode 1: fp32 out [c][nsp] + residual (x-layout) + FUSED tstats1 partial sums
// mode 3: write directly to x-layout output with residual from Res ([c][nsp])
__global__ void __launch_bounds__(256, 2) gemm_proj(
    const __nv_bfloat16* __restrict__ Wb, const float* __restrict__ bias,
    const __nv_bfloat16* __restrict__ Xb,
    float* __restrict__ OutF, const float* __restrict__ Res, int mode)
{
    extern __shared__ __align__(16) char sm[];
    const uint32_t sb = smem_u32(sm);
    const int tid = threadIdx.x, lane = tid & 31, wid = tid >> 5;
    const int wm = wid & 1, wn = wid >> 1;
    const int n0 = blockIdx.x << 7, m0 = blockIdx.y << 7;

    auto issue = [&](int kc, int st) {
        uint32_t sA = sb + st * STAGE_BYTES;
        uint32_t sB = sA + 16384;
#pragma unroll
        for (int i = 0; i < 4; i++) {
            int ch = tid + (i << 8);
            int rA = ch >> 3, cA = ch & 7;
            CP16(sA + swzA(rA, cA),
                 Wb + (size_t)(m0 + rA) * 512 + (kc << 6) + (cA << 3));
            int rB = ch >> 4, cB = ch & 15;
            CP16(sB + swzB(rB, cB),
                 Xb + (size_t)((kc << 6) + rB) * NSP + n0 + (cB << 3));
        }
    };

    float acc[4][4][4] = {};
    issue(0, 0); CP_COMMIT();
    issue(1, 1); CP_COMMIT();
    const int NK = 8;
    for (int s = 0; s < NK; s++) {
        CP_WAIT1();
        __syncthreads();
        if (s + 2 < NK) issue(s + 2, (s + 2) % 3);
        CP_COMMIT();
        uint32_t sA = sb + (s % 3) * STAGE_BYTES, sB = sA + 16384;
#pragma unroll
        for (int kk = 0; kk < 4; kk++) {
            uint32_t af[4][4], bf[2][4];
#pragma unroll
            for (int mt = 0; mt < 4; mt++) {
                int r = (wm << 6) + (mt << 4) + (lane & 15);
                int c16 = (kk << 1) + ((lane >> 4) & 1);
                ldsm4(af[mt], sA + swzA(r, c16));
            }
#pragma unroll
            for (int nb = 0; nb < 2; nb++) {
                int r = (kk << 4) + (lane & 15);
                int c16 = (wn << 2) + (nb << 1) + ((lane >> 4) & 1);
                ldsm4t(bf[nb], sB + swzB(r, c16));
            }
#pragma unroll
            for (int mt = 0; mt < 4; mt++)
#pragma unroll
                for (int ng = 0; ng < 4; ng++)
                    mma_bf16(acc[mt][ng], af[mt],
                             bf[ng >> 1][(ng & 1) << 1], bf[ng >> 1][((ng & 1) << 1) + 1]);
        }
    }

    const int g = lane >> 2, tig = lane & 3;
    if (mode == 1) {
        const int bt = n0 >> 10, bb = bt >> 4, tt = bt & 15;
#pragma unroll
        for (int mt = 0; mt < 4; mt++) {
            int mlo = m0 + (wm << 6) + (mt << 4) + g;
            float blo = __ldg(bias + mlo), bhi = __ldg(bias + mlo + 8);
#pragma unroll
            for (int ng = 0; ng < 4; ng++) {
                int n = n0 + (wn << 5) + (ng << 3) + (tig << 1);
                float* d = acc[mt][ng];
                float2 olo = make_float2(d[0] + blo, d[1] + blo);
                float2 ohi = make_float2(d[2] + bhi, d[3] + bhi);
                int hw = n & 1023;
                float2 rlo = *(const float2*)(Res +
                    (((size_t)((bb * CN + mlo) * 16 + tt)) << 10) + hw);
                float2 rhi = *(const float2*)(Res +
                    (((size_t)((bb * CN + mlo + 8) * 16 + tt)) << 10) + hw);
                olo.x += rlo.x; olo.y += rlo.y;
                ohi.x += rhi.x; ohi.y += rhi.y;
                *(float2*)(OutF + (size_t)mlo * NSP + n) = olo;
                *(float2*)(OutF + (size_t)(mlo + 8) * NSP + n) = ohi;
                float s0 = olo.x + ohi.x, s1 = olo.y + ohi.y;
                float q0 = olo.x * olo.x + ohi.x * ohi.x;
                float q1 = olo.y * olo.y + ohi.y * ohi.y;
#pragma unroll
                for (int off = 4; off <= 16; off <<= 1) {
                    s0 += __shfl_xor_sync(0xffffffffu, s0, off);
                    s1 += __shfl_xor_sync(0xffffffffu, s1, off);
                    q0 += __shfl_xor_sync(0xffffffffu, q0, off);
                    q1 += __shfl_xor_sync(0xffffffffu, q1, off);
                }
                if (g == 0) {
                    int grp = mlo >> 4;
                    size_t pbase = (((size_t)(bt * 32 + grp)) << 10) + hw;
                    g_ps [pbase]     = s0;
                    g_ps [pbase + 1] = s1;
                    g_ps2[pbase]     = q0;
                    g_ps2[pbase + 1] = q1;
                }
            }
        }
    } else {
        CP_WAIT0();
        __syncthreads();
        float* tile = (float*)sm;  // [128][129]
#pragma unroll
        for (int mt = 0; mt < 4; mt++) {
            int mrow = (wm << 6) + (mt << 4) + g;
            int mlo = m0 + mrow;
            float blo = __ldg(bias + mlo), bhi = __ldg(bias + mlo + 8);
#pragma unroll
            for (int ng = 0; ng < 4; ng++) {
                int nl = (wn << 5) + (ng << 3) + (tig << 1);
                float* d = acc[mt][ng];
                tile[mrow * 129 + nl]           = d[0] + blo;
                tile[mrow * 129 + nl + 1]       = d[1] + blo;
                tile[(mrow + 8) * 129 + nl]     = d[2] + bhi;
                tile[(mrow + 8) * 129 + nl + 1] = d[3] + bhi;
            }
        }
        __syncthreads();
        const int b = n0 >> 14;
        const int hw0 = (n0 >> 4) & 1023;
        for (int idx = tid; idx < 16384; idx += 256) {
            int hwl = idx & 7, t = (idx >> 3) & 15, m = idx >> 7;
            int c = m0 + m;
            float v = tile[m * 129 + hwl * 16 + t];
            float sres = Res[(size_t)c * NSP + ((size_t)((b << 4) + t) << 10) + hw0 + hwl];
            OutF[((size_t)((b * CN + c) * 16 + t) << 10) + hw0 + hwl] = v + sres;
        }
    }
}

// ===================== spatial logits GEMM ==================================
__global__ void __launch_bounds__(256, 2) gemm_logits(
    const __nv_bfloat16* __restrict__ Qb, const __nv_bfloat16* __restrict__ Kb,
    float* __restrict__ P)
{
    extern __shared__ __align__(16) char sm[];
    const uint32_t sb = smem_u32(sm);
    const int tid = threadIdx.x, lane = tid & 31, wid = tid >> 5;
    const int wm = wid & 1, wn = wid >> 1;
    const int n0 = blockIdx.x << 7, m0 = blockIdx.y << 7;
    const int base = blockIdx.z << 10;

    auto issue = [&](int kc, int st) {
        uint32_t sA = sb + st * STAGE_BYTES;
        uint32_t sB = sA + 16384;
#pragma unroll
        for (int i = 0; i < 4; i++) {
            int ch = tid + (i << 8);
            int r = ch >> 4, c = ch & 15;
            CP16(sA + swzB(r, c),
                 Qb + (size_t)((kc << 6) + r) * NSP + base + m0 + (c << 3));
            CP16(sB + swzB(r, c),
                 Kb + (size_t)((kc << 6) + r) * NSP + base + n0 + (c << 3));
        }
    };

    float acc[4][4][4] = {};
    issue(0, 0); CP_COMMIT();
    issue(1, 1); CP_COMMIT();
    const int NK = 8;
    for (int s = 0; s < NK; s++) {
        CP_WAIT1();
        __syncthreads();
        if (s + 2 < NK) issue(s + 2, (s + 2) % 3);
        CP_COMMIT();
        uint32_t sA = sb + (s % 3) * STAGE_BYTES, sB = sA + 16384;
#pragma unroll
        for (int kk = 0; kk < 4; kk++) {
            uint32_t af[4][4], bf[2][4];
#pragma unroll
            for (int mt = 0; mt < 4; mt++) {
                int r = (kk << 4) + (lane & 7) + (((lane >> 4) & 1) << 3);
                int c16 = (wm << 3) + (mt << 1) + ((lane >> 3) & 1);
                ldsm4t(af[mt], sA + swzB(r, c16));
            }
#pragma unroll
            for (int nb = 0; nb < 2; nb++) {
                int r = (kk << 4) + (lane & 15);
                int c16 = (wn << 2) + (nb << 1) + ((lane >> 4) & 1);
                ldsm4t(bf[nb], sB + swzB(r, c16));
            }
#pragma unroll
            for (int mt = 0; mt < 4; mt++)
#pragma unroll
                for (int ng = 0; ng < 4; ng++)
                    mma_bf16(acc[mt][ng], af[mt],
                             bf[ng >> 1][(ng & 1) << 1], bf[ng >> 1][((ng & 1) << 1) + 1]);
        }
    }

    float* Pb = P + ((size_t)blockIdx.z << 20);
    const int g = lane >> 2, tig = lane & 3;
#pragma unroll
    for (int mt = 0; mt < 4; mt++) {
        int mlo = m0 + (wm << 6) + (mt << 4) + g;
#pragma unroll
        for (int ng = 0; ng < 4; ng++) {
            int n = n0 + (wn << 5) + (ng << 3) + (tig << 1);
            float* d = acc[mt][ng];
            *(float2*)(Pb + (size_t)mlo * 1024 + n) =
                make_float2(d[0] * ATT_SCALE, d[1] * ATT_SCALE);
            *(float2*)(Pb + (size_t)(mlo + 8) * 1024 + n) =
                make_float2(d[2] * ATT_SCALE, d[3] * ATT_SCALE);
        }
    }
}

// ===================== attn @ V GEMM ========================================
__global__ void __launch_bounds__(256, 2) gemm_av(
    const __nv_bfloat16* __restrict__ Vb, const __nv_bfloat16* __restrict__ Pb,
    __nv_bfloat16* __restrict__ OutB)
{
    extern __shared__ __align__(16) char sm[];
    const uint32_t sb = smem_u32(sm);
    const int tid = threadIdx.x, lane = tid & 31, wid = tid >> 5;
    const int wm = wid & 1, wn = wid >> 1;
    const int n0 = blockIdx.x << 7, m0 = blockIdx.y << 7;
    const int base = blockIdx.z << 10;
    const __nv_bfloat16* Pt = Pb + ((size_t)blockIdx.z << 20);

    auto issue = [&](int kc, int st) {
        uint32_t sA = sb + st * STAGE_BYTES;
        uint32_t sB = sA + 16384;
#pragma unroll
        for (int i = 0; i < 4; i++) {
            int ch = tid + (i << 8);
            int r = ch >> 3, c = ch & 7;
            CP16(sA + swzA(r, c),
                 Vb + (size_t)(m0 + r) * NSP + base + (kc << 6) + (c << 3));
            CP16(sB + swzA(r, c),
                 Pt + (size_t)(n0 + r) * 1024 + (kc << 6) + (c << 3));
        }
    };

    float acc[4][4][4] = {};
    issue(0, 0); CP_COMMIT();
    issue(1, 1); CP_COMMIT();
    const int NK = 16;
    for (int s = 0; s < NK; s++) {
        CP_WAIT1();
        __syncthreads();
        if (s + 2 < NK) issue(s + 2, (s + 2) % 3);
        CP_COMMIT();
        uint32_t sA = sb + (s % 3) * STAGE_BYTES, sB = sA + 16384;
#pragma unroll
        for (int kk = 0; kk < 4; kk++) {
            uint32_t af[4][4], bf[2][4];
#pragma unroll
            for (int mt = 0; mt < 4; mt++) {
                int r = (wm << 6) + (mt << 4) + (lane & 15);
                int c16 = (kk << 1) + ((lane >> 4) & 1);
                ldsm4(af[mt], sA + swzA(r, c16));
            }
#pragma unroll
            for (int nb = 0; nb < 2; nb++) {
                int r = (wn << 5) + (nb << 4) + (lane & 7) + (((lane >> 4) & 1) << 3);
                int c16 = (kk << 1) + ((lane >> 3) & 1);
                ldsm4(bf[nb], sB + swzA(r, c16));
            }
#pragma unroll
            for (int mt = 0; mt < 4; mt++)
#pragma unroll
                for (int ng = 0; ng < 4; ng++)
                    mma_bf16(acc[mt][ng], af[mt],
                             bf[ng >> 1][(ng & 1) << 1], bf[ng >> 1][((ng & 1) << 1) + 1]);
        }
    }

    const int g = lane >> 2, tig = lane & 3;
#pragma unroll
    for (int mt = 0; mt < 4; mt++) {
        int mlo = m0 + (wm << 6) + (mt << 4) + g;
#pragma unroll
        for (int ng = 0; ng < 4; ng++) {
            int n = n0 + (wn << 5) + (ng << 3) + (tig << 1);
            float* d = acc[mt][ng];
            *(__nv_bfloat162*)(OutB + (size_t)mlo * NSP + base + n) =
                __floats2bfloat162_rn(d[0], d[1]);
            *(__nv_bfloat162*)(OutB + (size_t)(mlo + 8) * NSP + base + n) =
                __floats2bfloat162_rn(d[2], d[3]);
        }
    }
}

// ===================== weight fp32 -> bf16 (all 8 in one launch) ============
__global__ __launch_bounds__(256) void wcvt8(
    const float* w0, const float* w1, const float* w2, const float* w3,
    const float* w4, const float* w5, const float* w6, const float* w7,
    __nv_bfloat16* __restrict__ Wb)
{
    const float* ws[8] = {w0, w1, w2, w3, w4, w5, w6, w7};
    int wsel = blockIdx.y;
    int idx = (blockIdx.x * 256 + threadIdx.x) * 4;
    float4 v = *(const float4*)(ws[wsel] + idx);
    __nv_bfloat162 p0 = __floats2bfloat162_rn(v.x, v.y);
    __nv_bfloat162 p1 = __floats2bfloat162_rn(v.z, v.w);
    uint2 o;
    o.x = *(uint32_t*)&p0; o.y = *(uint32_t*)&p1;
    *(uint2*)(Wb + (size_t)wsel * CN * CN + idx) = o;
}

// ===================== spatial GroupNorm -> bf16 [c][n] (single pass) =======
__global__ __launch_bounds__(256) void gn_spatial(
    const float* __restrict__ x, const float* __restrict__ gamma,
    const float* __restrict__ beta, __nv_bfloat16* __restrict__ hsb)
{
    int bt = blockIdx.x >> 5, g = blockIdx.x & 31;
    int b = bt >> 4, t = bt & 15;
    int tid = threadIdx.x;
    float2 v[16][2];
    float s = 0.f, s2 = 0.f;
#pragma unroll
    for (int ci = 0; ci < 16; ci++) {
        const float* p = x + ((size_t)((b * CN + g * 16 + ci) * 16 + t) << 10);
#pragma unroll
        for (int j = 0; j < 2; j++) {
            float2 vv = *(const float2*)(p + 2 * tid + 512 * j);
            v[ci][j] = vv;
            s += vv.x + vv.y; s2 += vv.x * vv.x + vv.y * vv.y;
        }
    }
    __shared__ float red0[8], red1[8];
#pragma unroll
    for (int off = 16; off; off >>= 1) {
        s  += __shfl_xor_sync(0xffffffffu, s,  off);
        s2 += __shfl_xor_sync(0xffffffffu, s2, off);
    }
    if ((tid & 31) == 0) { red0[tid >> 5] = s; red1[tid >> 5] = s2; }
    __syncthreads();
    float S = 0.f, S2 = 0.f;
#pragma unroll
    for (int i = 0; i < 8; i++) { S += red0[i]; S2 += red1[i]; }
    float mean = S * (1.f / 16384.f);
    float var  = S2 * (1.f / 16384.f) - mean * mean;
    float rstd = rsqrtf(var + GN_EPS);
#pragma unroll
    for (int ci = 0; ci < 16; ci++) {
        int c = g * 16 + ci;
        __nv_bfloat16* q = hsb + (size_t)c * NSP + (bt << 10);
        float gm = gamma[c] * rstd, be = beta[c] - mean * gamma[c] * rstd;
#pragma unroll
        for (int j = 0; j < 2; j++) {
            *(__nv_bfloat162*)(q + 2 * tid + 512 * j) =
                __floats2bfloat162_rn(v[ci][j].x * gm + be, v[ci][j].y * gm + be);
        }
    }
}

// ===================== spatial softmax (fp32 -> bf16) =======================
__global__ __launch_bounds__(256) void softmax_k(const float* __restrict__ P,
                                                 __nv_bfloat16* __restrict__ Pb)
{
    int tid = threadIdx.x;
    const float4* r = (const float4*)(P + ((size_t)blockIdx.x << 10));
    float4 a = r[tid];
    float m = fmaxf(fmaxf(a.x, a.y), fmaxf(a.z, a.w));
    __shared__ float red[8];
#pragma unroll
    for (int off = 16; off; off >>= 1) m = fmaxf(m, __shfl_xor_sync(0xffffffffu, m, off));
    if ((tid & 31) == 0) red[tid >> 5] = m;
    __syncthreads();
    float M = red[0];
#pragma unroll
    for (int i = 1; i < 8; i++) M = fmaxf(M, red[i]);
    a.x = __expf(a.x - M); a.y = __expf(a.y - M);
    a.z = __expf(a.z - M); a.w = __expf(a.w - M);
    float s = a.x + a.y + a.z + a.w;
    __syncthreads();
#pragma unroll
    for (int off = 16; off; off >>= 1) s += __shfl_xor_sync(0xffffffffu, s, off);
    if ((tid & 31) == 0) red[tid >> 5] = s;
    __syncthreads();
    float S = red[0];
#pragma unroll
    for (int i = 1; i < 8; i++) S += red[i];
    float inv = 1.f / S;
    __nv_bfloat162 p0 = __floats2bfloat162_rn(a.x * inv, a.y * inv);
    __nv_bfloat162 p1 = __floats2bfloat162_rn(a.z * inv, a.w * inv);
    uint2 o; o.x = *(uint32_t*)&p0; o.y = *(uint32_t*)&p1;
    *(uint2*)(Pb + ((size_t)blockIdx.x << 10) + 4 * tid) = o;
}

// ===================== temporal stats (pass 2 only; pass 1 fused) ===========
__global__ __launch_bounds__(256) void tstats2()
{
    int hwc = blockIdx.x & 3, g = (blockIdx.x >> 2) & 31, b = blockIdx.x >> 7;
    int hw = (hwc << 8) + threadIdx.x;
    float s = 0.f, s2 = 0.f;
#pragma unroll
    for (int t = 0; t < 16; t++) {
        int idx = (((b * 16 + t) * 32 + g) << 10) + hw;
        s += g_ps[idx]; s2 += g_ps2[idx];
    }
    float mean = s * (1.f / 256.f);
    float var  = s2 * (1.f / 256.f) - mean * mean;
    int n = (b << 10) + hw;
    g_mean[n * 32 + g] = mean;
    g_rstd[n * 32 + g] = rsqrtf(var + GN_EPS);
}

// normalize + transpose into bf16 ht[c][(b,hw)*16+t]
__global__ __launch_bounds__(256) void tnorm(
    const float* __restrict__ S, const float* __restrict__ gamma,
    const float* __restrict__ beta, __nv_bfloat16* __restrict__ ht)
{
    __shared__ float sm[4 * 2176];
    __shared__ float smean[128], srstd[128];
    int hw0 = blockIdx.x << 7, c0 = blockIdx.y << 2, b = blockIdx.z;
    int g = c0 >> 4;
    int tid = threadIdx.x;
    if (tid < 128) {
        int n = (b << 10) + hw0 + tid;
        smean[tid] = g_mean[n * 32 + g];
        srstd[tid] = g_rstd[n * 32 + g];
    }
    __syncthreads();
    for (int idx = tid; idx < 8192; idx += 256) {
        int c = idx >> 11, rem = idx & 2047, t = rem >> 7, col = rem & 127;
        float v = S[(size_t)(c0 + c) * NSP + ((size_t)((b << 4) + t) << 10) + hw0 + col];
        float h = (v - smean[col]) * srstd[col] * gamma[c0 + c] + beta[c0 + c];
        sm[c * 2176 + col * 17 + t] = h;
    }
    __syncthreads();
    size_t base = (size_t)((b << 10) + hw0) << 4;
    for (int idx = tid; idx < 4096; idx += 256) {
        int c = idx >> 10, j2 = (idx & 1023) << 1;
        float v0 = sm[c * 2176 + ((j2 >> 4) * 17) + (j2 & 15)];
        float v1 = sm[c * 2176 + ((j2 >> 4) * 17) + (j2 & 15) + 1];
        *(__nv_bfloat162*)(ht + (size_t)(c0 + c) * NSP + base + j2) =
            __floats2bfloat162_rn(v0, v1);
    }
}

// ===================== temporal attention (bulk-load, 3 barriers) ===========
// smem: qT[16][520] bf16 | kT[16][520] bf16 | v[512][16] bf16 | p[16][17] f32
__global__ __launch_bounds__(256) void temporal_attn(
    const __nv_bfloat16* __restrict__ Q, const __nv_bfloat16* __restrict__ K,
    const __nv_bfloat16* __restrict__ V, __nv_bfloat16* __restrict__ O)
{
    extern __shared__ __align__(16) char tsm[];
    __nv_bfloat16* qT = (__nv_bfloat16*)tsm;             // [16][520]
    __nv_bfloat16* kT = (__nv_bfloat16*)(tsm + 16640);   // [16][520]
    __nv_bfloat16* vS = (__nv_bfloat16*)(tsm + 33280);   // [512][16]
    float* p = (float*)(tsm + 49664);                    // [16][17]
    const int col0 = blockIdx.x << 4;
    const int tid = threadIdx.x;

    // bulk load: Q,K transposed into 520-stride rows; V straight copy
    for (int i = tid; i < 1024; i += 256) {
        int c = i >> 1, half = i & 1;
        size_t goff = (size_t)c * NSP + col0 + (half << 3);
        uint4 a = *(const uint4*)(Q + goff);
        uint4 b = *(const uint4*)(K + goff);
        const __nv_bfloat16* pa = (const __nv_bfloat16*)&a;
        const __nv_bfloat16* pb = (const __nv_bfloat16*)&b;
#pragma unroll
        for (int j = 0; j < 8; j++) {
            int col = (half << 3) + j;
            qT[col * 520 + c] = pa[j];
            kT[col * 520 + c] = pb[j];
        }
        *(uint4*)(vS + (c << 4) + (half << 3)) = *(const uint4*)(V + goff);
    }
    __syncthreads();

    // logits: p[hi][lo] = sum_c Q[c][col0+hi] * K[c][col0+lo]
    {
        const int hi = tid >> 4, lo = tid & 15;
        const uint4* qr = (const uint4*)(qT + hi * 520);
        const uint4* kr = (const uint4*)(kT + lo * 520);
        float acc = 0.f;
#pragma unroll 8
        for (int cc = 0; cc < 64; cc++) {
            uint4 a = qr[cc], b = kr[cc];
            const __nv_bfloat162* pa = (const __nv_bfloat162*)&a;
            const __nv_bfloat162* pb = (const __nv_bfloat162*)&b;
#pragma unroll
            for (int j = 0; j < 4; j++) {
                float2 fa = __bfloat1622float2(pa[j]);
                float2 fb = __bfloat1622float2(pb[j]);
                acc = fmaf(fa.x, fb.x, acc);
                acc = fmaf(fa.y, fb.y, acc);
            }
        }
        p[hi * 17 + lo] = acc * ATT_SCALE;
    }
    __syncthreads();

    if (tid < 16) {
        float m = -1e30f;
#pragma unroll
        for (int j = 0; j < 16; j++) m = fmaxf(m, p[tid * 17 + j]);
        float s = 0.f;
#pragma unroll
        for (int j = 0; j < 16; j++) {
            float e = __expf(p[tid * 17 + j] - m);
            p[tid * 17 + j] = e; s += e;
        }
        float inv = 1.f / s;
#pragma unroll
        for (int j = 0; j < 16; j++) p[tid * 17 + j] *= inv;
    }
    __syncthreads();

    // output: O[c][col0+lo] = sum_t V[c][col0+t] * p[lo][t]
    {
        const int hi = tid >> 4, lo = tid & 15;
        float pr[16];
#pragma unroll
        for (int t = 0; t < 16; t++) pr[t] = p[lo * 17 + t];
#pragma unroll 4
        for (int i = 0; i < 32; i++) {
            int c = (hi << 5) + i;
            uint4 v0 = *(const uint4*)(vS + (c << 4));
            uint4 v1 = *(const uint4*)(vS + (c << 4) + 8);
            const __nv_bfloat162* q0 = (const __nv_bfloat162*)&v0;
            const __nv_bfloat162* q1 = (const __nv_bfloat162*)&v1;
            float o = 0.f;
#pragma unroll
            for (int j = 0; j < 4; j++) {
                float2 f0 = __bfloat1622float2(q0[j]);
                o = fmaf(f0.x, pr[j * 2], o);
                o = fmaf(f0.y, pr[j * 2 + 1], o);
            }
#pragma unroll
            for (int j = 0; j < 4; j++) {
                float2 f1 = __bfloat1622float2(q1[j]);
                o = fmaf(f1.x, pr[8 + j * 2], o);
                o = fmaf(f1.y, pr[8 + j * 2 + 1], o);
            }
            O[(size_t)c * NSP + col0 + lo] = __float2bfloat16(o);
        }
    }
}

// ===================== launch ===============================================
extern "C" void kernel_launch(void* const* d_in, const int* in_sizes, int n_in,
                              void* d_out, int out_size)
{
    const float* x       = (const float*)d_in[0];
    const float* gamma_s = (const float*)d_in[1];
    const float* beta_s  = (const float*)d_in[2];
    const float* wq_s    = (const float*)d_in[3];
    const float* bq_s    = (const float*)d_in[4];
    const float* wk_s    = (const float*)d_in[5];
    const float* bk_s    = (const float*)d_in[6];
    const float* wv_s    = (const float*)d_in[7];
    const float* bv_s    = (const float*)d_in[8];
    const float* wo_s    = (const float*)d_in[9];
    const float* bo_s    = (const float*)d_in[10];
    const float* gamma_t = (const float*)d_in[11];
    const float* beta_t  = (const float*)d_in[12];
    const float* wq_t    = (const float*)d_in[13];
    const float* bq_t    = (const float*)d_in[14];
    const float* wk_t    = (const float*)d_in[15];
    const float* bk_t    = (const float*)d_in[16];
    const float* wv_t    = (const float*)d_in[17];
    const float* bv_t    = (const float*)d_in[18];
    const float* wo_t    = (const float*)d_in[19];
    const float* bo_t    = (const float*)d_in[20];

    float *s, *attn;
    __nv_bfloat16 *hsb, *qb, *kb, *vb, *ob, *attnb, *wb;
    cudaGetSymbolAddress((void**)&s,     g_s);
    cudaGetSymbolAddress((void**)&attn,  g_attn);
    cudaGetSymbolAddress((void**)&hsb,   g_hsb);
    cudaGetSymbolAddress((void**)&qb,    g_qb);
    cudaGetSymbolAddress((void**)&kb,    g_kb);
    cudaGetSymbolAddress((void**)&vb,    g_vb);
    cudaGetSymbolAddress((void**)&ob,    g_ob);
    cudaGetSymbolAddress((void**)&attnb, g_attnb);
    cudaGetSymbolAddress((void**)&wb,    g_wb);

    cudaFuncSetAttribute(gemm_qkv,      cudaFuncAttributeMaxDynamicSharedMemorySize, SMEM_TOT);
    cudaFuncSetAttribute(gemm_proj,     cudaFuncAttributeMaxDynamicSharedMemorySize, SMEM_TOT);
    cudaFuncSetAttribute(gemm_logits,   cudaFuncAttributeMaxDynamicSharedMemorySize, SMEM_TOT);
    cudaFuncSetAttribute(gemm_av,       cudaFuncAttributeMaxDynamicSharedMemorySize, SMEM_TOT);
    cudaFuncSetAttribute(temporal_attn, cudaFuncAttributeMaxDynamicSharedMemorySize, TA_SMEM);

    // 1: weights
    wcvt8<<<dim3(256, 8), 256>>>(wq_s, wk_s, wv_s, wo_s, wq_t, wk_t, wv_t, wo_t, wb);

    dim3 gqkv(256, 4, 3);
    dim3 gp(256, 4);

    // ---- spatial ----
    gn_spatial<<<1024, 256>>>(x, gamma_s, beta_s, hsb);                       // 2
    gemm_qkv<<<gqkv, 256, SMEM_TOT>>>(wb, bq_s, bk_s, bv_s, hsb, qb, kb, vb); // 3
    gemm_logits<<<dim3(8, 8, 32), 256, SMEM_TOT>>>(qb, kb, attn);             // 4
    softmax_k<<<32768, 256>>>(attn, attnb);                                   // 5
    gemm_av<<<dim3(8, 4, 32), 256, SMEM_TOT>>>(vb, attnb, ob);                // 6 <- ncu
    gemm_proj<<<gp, 256, SMEM_TOT>>>(wb + 3 * CN * CN, bo_s, ob, s, x, 1);    // 7 (+tstats1)

    // ---- temporal ----
    tstats2<<<256, 256>>>();
    tnorm<<<dim3(8, 128, 2), 256>>>(s, gamma_t, beta_t, hsb);
    gemm_qkv<<<gqkv, 256, SMEM_TOT>>>(wb + 4 * CN * CN, bq_t, bk_t, bv_t, hsb, qb, kb, vb);
    temporal_attn<<<2048, 256, TA_SMEM>>>(qb, kb, vb, ob);
    gemm_proj<<<gp, 256, SMEM_TOT>>>(wb + 7 * CN * CN, bo_t, ob, (float*)d_out, s, 3);
}